// round 15
// baseline (speedup 1.0000x reference)
#include <cuda_runtime.h>
#include <math.h>

#define GRIDW 64
#define PADW  67              // 1 low pad + 2 high pad (tent taps reach x0+2)
#define CIN   80
#define HID   64
#define SPR   96
#define NRAY  4096
#define NPTS  (NRAY*SPR)
#define PLANE_TEXELS (PADW*PADW)
#define PLANE_FLOATS (PLANE_TEXELS*HID)
#define SETUP_ITEMS (3*PLANE_TEXELS*16)
#define GEMM_BLOCKS 384
#define SETUP_BLOCKS 64

// W1-projected planes, zero-padded border: [p][y+1][x+1][j]
__device__ float g_PL[3*PLANE_FLOATS];
// per-point scratch: [point][8] = {rgb0,rgb1,rgb2,sigma, n0,n1,n2,pad}
__device__ float g_scr[NPTS*8];
// per-ray packed params: [ray*2] = (ro+tn*rd, tn), [ray*2+1] = (span*rd, span)
__device__ float4 g_rayp[NRAY*2];
// transposed W2: W2T[c][j] = W2[j][c]
__device__ float g_W2T[4*64];

__device__ __forceinline__ float sum32(float v) {
    #pragma unroll
    for (int off = 16; off; off >>= 1)
        v += __shfl_xor_sync(0xffffffffu, v, off);
    return v;
}

// ---------------------------------------------------------------------------
// Kernel 1 (merged): blocks [0,384): GEMM  PL[p][y+1][x+1][jbase+j4]
//                    blocks [384,448): grid-stride setup (borders, W2T, rays)
// ---------------------------------------------------------------------------
__global__ __launch_bounds__(512) void project_planes(
        const float* __restrict__ planes,
        const float* __restrict__ W1,
        const float* __restrict__ W2,
        const float* __restrict__ ro_all,
        const float* __restrict__ rd_all) {
    const int tid = threadIdx.x;
    if (blockIdx.x >= GEMM_BLOCKS) {
        const int base = (blockIdx.x - GEMM_BLOCKS) * 512 + tid;
        for (int i = base; i < SETUP_ITEMS; i += SETUP_BLOCKS * 512) {
            if (i < 256) {
                const int c = i >> 6, j = i & 63;
                g_W2T[c*64 + j] = W2[j*4 + c];
            }
            if (i < NRAY) {
                const int r = i;
                const float ro0 = ro_all[r*3+0], ro1 = ro_all[r*3+1], ro2 = ro_all[r*3+2];
                const float rd0 = rd_all[r*3+0], rd1 = rd_all[r*3+1], rd2 = rd_all[r*3+2];
                float tn = 0.f, tf = 3.402823e38f;
                const float o[3] = {ro0, ro1, ro2};
                const float d[3] = {rd0, rd1, rd2};
                #pragma unroll
                for (int k = 0; k < 3; k++) {
                    float srd = (fabsf(d[k]) < 1e-9f) ? 1e-9f : d[k];
                    float ta = (-0.6f - o[k]) / srd;
                    float tb = ( 0.6f - o[k]) / srd;
                    tn = fmaxf(tn, fminf(ta, tb));
                    tf = fminf(tf, fmaxf(ta, tb));
                }
                const float span = fmaxf(tf - tn, 0.f);
                g_rayp[r*2]   = make_float4(fmaf(tn, rd0, ro0), fmaf(tn, rd1, ro1), fmaf(tn, rd2, ro2), tn);
                g_rayp[r*2+1] = make_float4(span*rd0, span*rd1, span*rd2, span);
            }
            const int tex = i >> 4;
            const int q   = i & 15;
            const int t   = tex % PLANE_TEXELS;
            const int y   = t / PADW;
            const int x   = t - y*PADW;
            if (x == 0 || x >= PADW-2 || y == 0 || y >= PADW-2) {
                float4 z; z.x = z.y = z.z = z.w = 0.f;
                *reinterpret_cast<float4*>(&g_PL[(size_t)tex*HID + q*4]) = z;
            }
        }
        return;
    }
    const int blk = blockIdx.x;           // 0..383
    const int p     = blk >> 7;           // 0..2
    const int rem   = blk & 127;
    const int y     = rem >> 1;           // 0..63
    const int jbase = (rem & 1) * 32;     // 0 or 32
    __shared__ float feats[CIN][GRIDW];   // 20 KB
    __shared__ float w1s[CIN][32];        // 10 KB
    for (int i = tid; i < CIN*GRIDW; i += 512) {
        int c = i >> 6, x = i & 63;
        feats[c][x] = planes[(((p*CIN + c)*GRIDW) + y)*GRIDW + x];
    }
    for (int i = tid; i < CIN*32; i += 512) {
        int c = i >> 5, j = i & 31;
        w1s[c][j] = W1[(p*CIN + c)*HID + jbase + j];
    }
    __syncthreads();
    const int x  = tid >> 3;              // 0..63
    const int j4 = (tid & 7) * 4;         // 0..28
    // two independent accumulation chains (c and c+40) for 2x ILP
    float a0 = 0.f, a1 = 0.f, a2 = 0.f, a3 = 0.f;
    float b0 = 0.f, b1a = 0.f, b2a = 0.f, b3 = 0.f;
    #pragma unroll 8
    for (int c = 0; c < CIN/2; c++) {
        const float f0 = feats[c][x];
        const float f1 = feats[c + 40][x];
        const float4 wA = *reinterpret_cast<const float4*>(&w1s[c][j4]);
        const float4 wB = *reinterpret_cast<const float4*>(&w1s[c + 40][j4]);
        a0 = fmaf(f0, wA.x, a0);
        a1 = fmaf(f0, wA.y, a1);
        a2 = fmaf(f0, wA.z, a2);
        a3 = fmaf(f0, wA.w, a3);
        b0 = fmaf(f1, wB.x, b0);
        b1a = fmaf(f1, wB.y, b1a);
        b2a = fmaf(f1, wB.z, b2a);
        b3 = fmaf(f1, wB.w, b3);
    }
    float4 v; v.x = a0 + b0; v.y = a1 + b1a; v.z = a2 + b2a; v.w = a3 + b3;
    *reinterpret_cast<float4*>(
        &g_PL[((size_t)p*PLANE_TEXELS + (size_t)(y+1)*PADW + (x+1))*HID + jbase + j4]) = v;
}

// ---------------------------------------------------------------------------
// axis helper: base floor index (padded), base frac w, FD frac t (vs same floor)
// ---------------------------------------------------------------------------
struct Ax { int i1; float w; float t; };
__device__ __forceinline__ Ax mkax(float p) {
    const float SCL32 = (2.0f/1.2f) * 32.f;
    const float f  = fmaf(p, SCL32, 31.5f);
    const float fl = floorf(f);
    const float qc = fminf(fmaxf(p + 0.01f, -0.6f), 0.6f);
    const float fq = fmaf(qc, SCL32, 31.5f);
    Ax a;
    a.i1 = (int)fl + 1;
    a.w  = f - fl;
    a.t  = fq - fl;                 // in [0, 2)
    return a;
}

#define ACC4(D, W, V) \
    D.x = fmaf((W), (V).x, D.x); D.y = fmaf((W), (V).y, D.y); \
    D.z = fmaf((W), (V).z, D.z); D.w = fmaf((W), (V).w, D.w);

// One plane: 8-texel L-footprint, unconditional loads.
// Base partial -> temp T, added into Bb and Bw at the end. FD-u -> Bu; FD-v -> Bv.
__device__ __forceinline__ void do_plane(const float* __restrict__ tp,
        const Ax U, const Ax V,
        float4& Bb, float4& Bw, float4& Bu, float4& Bv) {
    const float bx0 = 1.f - U.w, bx1 = U.w;
    const float by0 = 1.f - V.w, by1 = V.w;
    const float qu0 = fmaxf(1.f - U.t, 0.f);
    const float qu1 = 1.f - fabsf(U.t - 1.f);
    const float qu2 = fmaxf(U.t - 1.f, 0.f);
    const float qv0 = fmaxf(1.f - V.t, 0.f);
    const float qv1 = 1.f - fabsf(V.t - 1.f);
    const float qv2 = fmaxf(V.t - 1.f, 0.f);
    float4 T = {0.f, 0.f, 0.f, 0.f};
    #define TEXEL(i, j) (*reinterpret_cast<const float4*>(tp + ((j)*PADW + (i))*HID))
    {   const float4 v = TEXEL(0,0);
        const float wb = bx0*by0, wu = qu0*by0, wv = bx0*qv0;
        ACC4(T, wb, v) ACC4(Bu, wu, v) ACC4(Bv, wv, v)
    }
    {   const float4 v = TEXEL(1,0);
        const float wb = bx1*by0, wu = qu1*by0, wv = bx1*qv0;
        ACC4(T, wb, v) ACC4(Bu, wu, v) ACC4(Bv, wv, v)
    }
    {   const float4 v = TEXEL(2,0);
        ACC4(Bu, qu2*by0, v)
    }
    {   const float4 v = TEXEL(0,1);
        const float wb = bx0*by1, wu = qu0*by1, wv = bx0*qv1;
        ACC4(T, wb, v) ACC4(Bu, wu, v) ACC4(Bv, wv, v)
    }
    {   const float4 v = TEXEL(1,1);
        const float wb = bx1*by1, wu = qu1*by1, wv = bx1*qv1;
        ACC4(T, wb, v) ACC4(Bu, wu, v) ACC4(Bv, wv, v)
    }
    {   const float4 v = TEXEL(2,1);
        ACC4(Bu, qu2*by1, v)
    }
    {   const float4 v = TEXEL(0,2);
        ACC4(Bv, bx0*qv2, v)
    }
    {   const float4 v = TEXEL(1,2);
        ACC4(Bv, bx1*qv2, v)
    }
    #undef TEXEL
    Bb.x += T.x; Bb.y += T.y; Bb.z += T.z; Bb.w += T.w;
    Bw.x += T.x; Bw.y += T.y; Bw.z += T.z; Bw.w += T.w;
}

// ---------------------------------------------------------------------------
// Kernel 2: 2 points per warp, 16 lanes/point, 4 channels/lane.
// Each 16-point block lies in exactly one ray (96 % 16 == 0).
// ---------------------------------------------------------------------------
__global__ __launch_bounds__(256, 5) void point_kernel(
        const float* __restrict__ b1,
        const float* __restrict__ b2,
        float* __restrict__ grad_out) {
    const int lane = threadIdx.x & 31;
    const int sub  = lane & 15;
    const int ray   = blockIdx.x / 6;                       // magic-mul, no div
    const int s     = (blockIdx.x - ray*6) * 16 + (threadIdx.x >> 5) * 2 + (lane >> 4);
    const int point = ray * SPR + s;

    const float4 A4 = g_rayp[ray*2];
    const float4 B4 = g_rayp[ray*2+1];
    const float frac = ((float)s + 0.5f) * (1.0f/96.0f);
    const float px = fmaf(B4.x, frac, A4.x);
    const float py = fmaf(B4.y, frac, A4.y);
    const float pz = fmaf(B4.z, frac, A4.z);
    const float pn2 = fmaf(px, px, fmaf(py, py, pz*pz));

    const Ax X = mkax(px);
    const Ax Y = mkax(py);
    const Ax Z = mkax(pz);

    // epilogue weights loaded early: ~600 cycles of FMA below to hide them
    const float4 b1v = *reinterpret_cast<const float4*>(b1 + sub*4);
    const float4 wc0 = *reinterpret_cast<const float4*>(&g_W2T[0*64 + sub*4]);
    const float4 wc1 = *reinterpret_cast<const float4*>(&g_W2T[1*64 + sub*4]);
    const float4 wc2 = *reinterpret_cast<const float4*>(&g_W2T[2*64 + sub*4]);
    const float4 wc3 = *reinterpret_cast<const float4*>(&g_W2T[3*64 + sub*4]);

    // b1 baked into the accumulator init (each H receives +b1 exactly once)
    float4 Hb = b1v, Hx = b1v, Hy = b1v, Hz = b1v;

    const float* PLL = g_PL + sub*4;
    // plane0 (x,y): base->Hb,Hz ; xFD->Hx ; yFD->Hy
    do_plane(PLL + ((size_t)0*PLANE_TEXELS + (size_t)Y.i1*PADW + X.i1)*HID,
             X, Y, Hb, Hz, Hx, Hy);
    // plane1 (x,z): base->Hb,Hy ; xFD->Hx ; zFD->Hz
    do_plane(PLL + ((size_t)1*PLANE_TEXELS + (size_t)Z.i1*PADW + X.i1)*HID,
             X, Z, Hb, Hy, Hx, Hz);
    // plane2 (y,z): base->Hb,Hx ; yFD->Hy ; zFD->Hz
    do_plane(PLL + ((size_t)2*PLANE_TEXELS + (size_t)Z.i1*PADW + Y.i1)*HID,
             Y, Z, Hb, Hx, Hy, Hz);

    const float hb0 = fmaxf(Hb.x, 0.f);
    const float hb1 = fmaxf(Hb.y, 0.f);
    const float hb2 = fmaxf(Hb.z, 0.f);
    const float hb3 = fmaxf(Hb.w, 0.f);
    const float hx0 = fmaxf(Hx.x, 0.f);
    const float hx1 = fmaxf(Hx.y, 0.f);
    const float hx2 = fmaxf(Hx.z, 0.f);
    const float hx3 = fmaxf(Hx.w, 0.f);
    const float hy0 = fmaxf(Hy.x, 0.f);
    const float hy1 = fmaxf(Hy.y, 0.f);
    const float hy2 = fmaxf(Hy.z, 0.f);
    const float hy3 = fmaxf(Hy.w, 0.f);
    const float hz0 = fmaxf(Hz.x, 0.f);
    const float hz1 = fmaxf(Hz.y, 0.f);
    const float hz2 = fmaxf(Hz.z, 0.f);
    const float hz3 = fmaxf(Hz.w, 0.f);

    const float v0 = fmaf(hb0,wc0.x, fmaf(hb1,wc0.y, fmaf(hb2,wc0.z, hb3*wc0.w)));
    const float v1 = fmaf(hb0,wc1.x, fmaf(hb1,wc1.y, fmaf(hb2,wc1.z, hb3*wc1.w)));
    const float v2 = fmaf(hb0,wc2.x, fmaf(hb1,wc2.y, fmaf(hb2,wc2.z, hb3*wc2.w)));
    const float v3 = fmaf(hb0,wc3.x, fmaf(hb1,wc3.y, fmaf(hb2,wc3.z, hb3*wc3.w)));
    const float vx = fmaf(hx0,wc0.x, fmaf(hx1,wc0.y, fmaf(hx2,wc0.z, hx3*wc0.w)));
    const float vy = fmaf(hy0,wc0.x, fmaf(hy1,wc0.y, fmaf(hy2,wc0.z, hy3*wc0.w)));
    const float vz = fmaf(hz0,wc0.x, fmaf(hz1,wc0.y, fmaf(hz2,wc0.z, hz3*wc0.w)));

    // --- packed multi-value reduction over 16 lanes (values: v0..v3,vx,vy,vz,0)
    const bool lo1 = (lane & 1) == 0;
    float s0 = lo1 ? vx : v0;
    float s1 = lo1 ? vy : v1;
    float s2 = lo1 ? vz : v2;
    float s3 = lo1 ? 0.f : v3;
    s0 = __shfl_xor_sync(0xffffffffu, s0, 1);
    s1 = __shfl_xor_sync(0xffffffffu, s1, 1);
    s2 = __shfl_xor_sync(0xffffffffu, s2, 1);
    s3 = __shfl_xor_sync(0xffffffffu, s3, 1);
    const float a0 = (lo1 ? v0 : vx) + s0;
    const float a1 = (lo1 ? v1 : vy) + s1;
    const float a2 = (lo1 ? v2 : vz) + s2;
    const float a3 = (lo1 ? v3 : 0.f) + s3;
    const bool lo2 = ((lane >> 1) & 1) == 0;
    float u0 = lo2 ? a2 : a0;
    float u1 = lo2 ? a3 : a1;
    u0 = __shfl_xor_sync(0xffffffffu, u0, 2);
    u1 = __shfl_xor_sync(0xffffffffu, u1, 2);
    const float c0 = (lo2 ? a0 : a2) + u0;
    const float c1 = (lo2 ? a1 : a3) + u1;
    const bool lo3 = ((lane >> 2) & 1) == 0;
    float w = lo3 ? c1 : c0;
    w = __shfl_xor_sync(0xffffffffu, w, 4);
    float dsum = (lo3 ? c0 : c1) + w;
    dsum += __shfl_xor_sync(0xffffffffu, dsum, 8);
    // value j lives at half-lane L(j) = bitrev3(j): {0,4,2,6,1,5,3,7}
    const int hb16 = lane & 16;
    const float4 b2v = *reinterpret_cast<const float4*>(b2);
    const float sdf_base = __shfl_sync(0xffffffffu, dsum, hb16 + 0) + b2v.x;
    const float rgb1v    = __shfl_sync(0xffffffffu, dsum, hb16 + 4) + b2v.y;
    const float rgb2v    = __shfl_sync(0xffffffffu, dsum, hb16 + 2) + b2v.z;
    const float rgb3v    = __shfl_sync(0xffffffffu, dsum, hb16 + 6) + b2v.w;
    const float sdfx     = __shfl_sync(0xffffffffu, dsum, hb16 + 1) + b2v.x;
    const float sdfy     = __shfl_sync(0xffffffffu, dsum, hb16 + 5) + b2v.x;
    const float sdfz     = __shfl_sync(0xffffffffu, dsum, hb16 + 3) + b2v.x;

    if (sub == 0) {
        const float g0 = (sdfx - sdf_base) * 100.f;
        const float g1 = (sdfy - sdf_base) * 100.f;
        const float g2 = (sdfz - sdf_base) * 100.f;
        grad_out[point*3 + 0] = g0;
        grad_out[point*3 + 1] = g1;
        grad_out[point*3 + 2] = g2;
        const float gn  = sqrtf(g0*g0 + g1*g1 + g2*g2);
        const float inv = __fdividef(1.f, gn + 1e-8f);
        const float shifted = sdf_base + sqrtf(pn2) - 0.5f;
        const float xs = -shifted * 80.f;
        const float sigma = fmaxf(xs, 0.f) + __logf(1.f + __expf(-fabsf(xs)));
        const float r1 = __fdividef(1.002f, 1.f + __expf(-rgb1v)) - 0.001f;
        const float r2 = __fdividef(1.002f, 1.f + __expf(-rgb2v)) - 0.001f;
        const float r3 = __fdividef(1.002f, 1.f + __expf(-rgb3v)) - 0.001f;
        float4 A; A.x = r1; A.y = r2; A.z = r3; A.w = sigma;
        float4 B; B.x = g0*inv; B.y = g1*inv; B.z = g2*inv; B.w = 0.f;
        *reinterpret_cast<float4*>(&g_scr[point*8    ]) = A;
        *reinterpret_cast<float4*>(&g_scr[point*8 + 4]) = B;
    }
}

// ---------------------------------------------------------------------------
// Kernel 3: warp-per-ray compositing via multiplicative prefix scan.
// ---------------------------------------------------------------------------
__global__ void composite(float* __restrict__ out) {
    const int lane = threadIdx.x & 31;
    const int r = blockIdx.x * 8 + (threadIdx.x >> 5);

    const float tn   = g_rayp[r*2].w;
    const float span = g_rayp[r*2+1].w;
    const float delta = span * (1.0f/96.0f);

    float rgb0=0.f, rgb1=0.f, rgb2=0.f, dep=0.f, ws=0.f, n0=0.f, n1=0.f, n2=0.f;
    float Tpre = 1.f;
    #pragma unroll
    for (int k = 0; k < 3; k++) {
        const int s = k*32 + lane;
        const float4 A = *reinterpret_cast<const float4*>(&g_scr[(size_t)(r*SPR + s)*8]);
        const float4 B = *reinterpret_cast<const float4*>(&g_scr[(size_t)(r*SPR + s)*8 + 4]);
        const float e = __expf(-A.w * delta);
        const float m = e + 1e-10f;
        const float alpha = 1.f - e;
        float incl = m;
        #pragma unroll
        for (int off = 1; off < 32; off <<= 1) {
            float t = __shfl_up_sync(0xffffffffu, incl, off);
            if (lane >= off) incl *= t;
        }
        float excl = __shfl_up_sync(0xffffffffu, incl, 1);
        if (lane == 0) excl = 1.f;
        const float tot = __shfl_sync(0xffffffffu, incl, 31);
        const float T = Tpre * excl;
        const float w = alpha * T;
        rgb0 = fmaf(w, A.x, rgb0);
        rgb1 = fmaf(w, A.y, rgb1);
        rgb2 = fmaf(w, A.z, rgb2);
        dep  = fmaf(w, tn + span * (((float)s + 0.5f) * (1.0f/96.0f)), dep);
        ws  += w;
        n0 = fmaf(w, B.x, n0);
        n1 = fmaf(w, B.y, n1);
        n2 = fmaf(w, B.z, n2);
        Tpre *= tot;
    }
    rgb0 = sum32(rgb0);
    rgb1 = sum32(rgb1);
    rgb2 = sum32(rgb2);
    dep  = sum32(dep);
    ws   = sum32(ws);
    n0   = sum32(n0);
    n1   = sum32(n1);
    n2   = sum32(n2);

    if (lane == 0) {
        const float bg = 1.f - ws;
        const float nn  = sqrtf(n0*n0 + n1*n1 + n2*n2);
        const float inv = __fdividef(1.f, nn + 1e-8f);
        out[r]         = rgb0 + bg;
        out[ 4096 + r] = rgb1 + bg;
        out[ 8192 + r] = rgb2 + bg;
        out[12288 + r] = dep;
        out[16384 + r] = ws;
        out[20480 + r] = ((n0*inv) + 1.f) * 0.5f * ws;
        out[24576 + r] = ((n1*inv) + 1.f) * 0.5f * ws;
        out[28672 + r] = ((n2*inv) + 1.f) * 0.5f * ws;
    }
}

// ---------------------------------------------------------------------------
extern "C" void kernel_launch(void* const* d_in, const int* in_sizes, int n_in,
                              void* d_out, int out_size) {
    const float* planes = (const float*)d_in[0];
    const float* ro     = (const float*)d_in[1];
    const float* rd     = (const float*)d_in[2];
    const float* W1     = (const float*)d_in[3];
    const float* b1     = (const float*)d_in[4];
    const float* W2     = (const float*)d_in[5];
    const float* b2     = (const float*)d_in[6];
    float* out = (float*)d_out;

    project_planes<<<GEMM_BLOCKS + SETUP_BLOCKS, 512>>>(planes, W1, W2, ro, rd);
    point_kernel<<<NPTS/16, 256>>>(b1, b2, out + 32768);
    composite<<<NRAY/8, 256>>>(out);
}

// round 16
// speedup vs baseline: 1.0984x; 1.0984x over previous
#include <cuda_runtime.h>
#include <math.h>

#define GRIDW 64
#define PADW  67              // 1 low pad + 2 high pad (tent taps reach x0+2)
#define CIN   80
#define HID   64
#define SPR   96
#define NRAY  4096
#define NPTS  (NRAY*SPR)
#define PLANE_TEXELS (PADW*PADW)
#define PLANE_FLOATS (PLANE_TEXELS*HID)
#define SETUP_ITEMS (3*PLANE_TEXELS*16)
#define GEMM_BLOCKS 384
#define SETUP_BLOCKS 64

// W1-projected planes, zero-padded border: [p][y+1][x+1][j]
__device__ float g_PL[3*PLANE_FLOATS];
// per-point scratch: [point][8] = {rgb0,rgb1,rgb2,sigma, n0,n1,n2,pad}
__device__ float g_scr[NPTS*8];
// per-ray packed params: [ray*2] = (ro+tn*rd, tn), [ray*2+1] = (span*rd, span)
__device__ float4 g_rayp[NRAY*2];
// transposed W2: W2T[c][j] = W2[j][c]
__device__ float g_W2T[4*64];

__device__ __forceinline__ float sum32(float v) {
    #pragma unroll
    for (int off = 16; off; off >>= 1)
        v += __shfl_xor_sync(0xffffffffu, v, off);
    return v;
}

// ---------------------------------------------------------------------------
// Kernel 1 (merged): blocks [0,384): GEMM  PL[p][y+1][x+1][jbase+j4]
//                    blocks [384,448): grid-stride setup (borders, W2T, rays)
// ---------------------------------------------------------------------------
__global__ __launch_bounds__(512) void project_planes(
        const float* __restrict__ planes,
        const float* __restrict__ W1,
        const float* __restrict__ W2,
        const float* __restrict__ ro_all,
        const float* __restrict__ rd_all) {
    const int tid = threadIdx.x;
    if (blockIdx.x >= GEMM_BLOCKS) {
        const int base = (blockIdx.x - GEMM_BLOCKS) * 512 + tid;
        for (int i = base; i < SETUP_ITEMS; i += SETUP_BLOCKS * 512) {
            if (i < 256) {
                const int c = i >> 6, j = i & 63;
                g_W2T[c*64 + j] = W2[j*4 + c];
            }
            if (i < NRAY) {
                const int r = i;
                const float ro0 = ro_all[r*3+0], ro1 = ro_all[r*3+1], ro2 = ro_all[r*3+2];
                const float rd0 = rd_all[r*3+0], rd1 = rd_all[r*3+1], rd2 = rd_all[r*3+2];
                float tn = 0.f, tf = 3.402823e38f;
                const float o[3] = {ro0, ro1, ro2};
                const float d[3] = {rd0, rd1, rd2};
                #pragma unroll
                for (int k = 0; k < 3; k++) {
                    float srd = (fabsf(d[k]) < 1e-9f) ? 1e-9f : d[k];
                    float ta = (-0.6f - o[k]) / srd;
                    float tb = ( 0.6f - o[k]) / srd;
                    tn = fmaxf(tn, fminf(ta, tb));
                    tf = fminf(tf, fmaxf(ta, tb));
                }
                const float span = fmaxf(tf - tn, 0.f);
                g_rayp[r*2]   = make_float4(fmaf(tn, rd0, ro0), fmaf(tn, rd1, ro1), fmaf(tn, rd2, ro2), tn);
                g_rayp[r*2+1] = make_float4(span*rd0, span*rd1, span*rd2, span);
            }
            const int tex = i >> 4;
            const int q   = i & 15;
            const int t   = tex % PLANE_TEXELS;
            const int y   = t / PADW;
            const int x   = t - y*PADW;
            if (x == 0 || x >= PADW-2 || y == 0 || y >= PADW-2) {
                float4 z; z.x = z.y = z.z = z.w = 0.f;
                *reinterpret_cast<float4*>(&g_PL[(size_t)tex*HID + q*4]) = z;
            }
        }
        return;
    }
    const int blk = blockIdx.x;           // 0..383
    const int p     = blk >> 7;           // 0..2
    const int rem   = blk & 127;
    const int y     = rem >> 1;           // 0..63
    const int jbase = (rem & 1) * 32;     // 0 or 32
    __shared__ float feats[CIN][GRIDW];   // 20 KB
    __shared__ float w1s[CIN][32];        // 10 KB
    for (int i = tid; i < CIN*GRIDW; i += 512) {
        int c = i >> 6, x = i & 63;
        feats[c][x] = planes[(((p*CIN + c)*GRIDW) + y)*GRIDW + x];
    }
    for (int i = tid; i < CIN*32; i += 512) {
        int c = i >> 5, j = i & 31;
        w1s[c][j] = W1[(p*CIN + c)*HID + jbase + j];
    }
    __syncthreads();
    const int x  = tid >> 3;              // 0..63
    const int j4 = (tid & 7) * 4;         // 0..28
    float a0 = 0.f, a1 = 0.f, a2 = 0.f, a3 = 0.f;
    #pragma unroll 8
    for (int c = 0; c < CIN; c++) {
        const float f = feats[c][x];
        const float4 w = *reinterpret_cast<const float4*>(&w1s[c][j4]);
        a0 = fmaf(f, w.x, a0);
        a1 = fmaf(f, w.y, a1);
        a2 = fmaf(f, w.z, a2);
        a3 = fmaf(f, w.w, a3);
    }
    float4 v; v.x = a0; v.y = a1; v.z = a2; v.w = a3;
    *reinterpret_cast<float4*>(
        &g_PL[((size_t)p*PLANE_TEXELS + (size_t)(y+1)*PADW + (x+1))*HID + jbase + j4]) = v;
}

// ---------------------------------------------------------------------------
// axis helper: base floor index (padded), base frac w, FD frac t (vs same floor)
// ---------------------------------------------------------------------------
struct Ax { int i1; float w; float t; };
__device__ __forceinline__ Ax mkax(float p) {
    const float SCL32 = (2.0f/1.2f) * 32.f;
    const float f  = fmaf(p, SCL32, 31.5f);
    const float fl = floorf(f);
    const float qc = fminf(fmaxf(p + 0.01f, -0.6f), 0.6f);
    const float fq = fmaf(qc, SCL32, 31.5f);
    Ax a;
    a.i1 = (int)fl + 1;
    a.w  = f - fl;
    a.t  = fq - fl;                 // in [0, 2)
    return a;
}

#define ACC4(D, W, V) \
    D.x = fmaf((W), (V).x, D.x); D.y = fmaf((W), (V).y, D.y); \
    D.z = fmaf((W), (V).z, D.z); D.w = fmaf((W), (V).w, D.w);

// One plane: 8-texel L-footprint, unconditional loads.
// Base partial -> temp T, added into Bb and Bw at the end. FD-u -> Bu; FD-v -> Bv.
__device__ __forceinline__ void do_plane(const float* __restrict__ tp,
        const Ax U, const Ax V,
        float4& Bb, float4& Bw, float4& Bu, float4& Bv) {
    const float bx0 = 1.f - U.w, bx1 = U.w;
    const float by0 = 1.f - V.w, by1 = V.w;
    const float qu0 = fmaxf(1.f - U.t, 0.f);
    const float qu1 = 1.f - fabsf(U.t - 1.f);
    const float qu2 = fmaxf(U.t - 1.f, 0.f);
    const float qv0 = fmaxf(1.f - V.t, 0.f);
    const float qv1 = 1.f - fabsf(V.t - 1.f);
    const float qv2 = fmaxf(V.t - 1.f, 0.f);
    float4 T = {0.f, 0.f, 0.f, 0.f};
    #define TEXEL(i, j) (*reinterpret_cast<const float4*>(tp + ((j)*PADW + (i))*HID))
    {   const float4 v = TEXEL(0,0);
        const float wb = bx0*by0, wu = qu0*by0, wv = bx0*qv0;
        ACC4(T, wb, v) ACC4(Bu, wu, v) ACC4(Bv, wv, v)
    }
    {   const float4 v = TEXEL(1,0);
        const float wb = bx1*by0, wu = qu1*by0, wv = bx1*qv0;
        ACC4(T, wb, v) ACC4(Bu, wu, v) ACC4(Bv, wv, v)
    }
    {   const float4 v = TEXEL(2,0);
        ACC4(Bu, qu2*by0, v)
    }
    {   const float4 v = TEXEL(0,1);
        const float wb = bx0*by1, wu = qu0*by1, wv = bx0*qv1;
        ACC4(T, wb, v) ACC4(Bu, wu, v) ACC4(Bv, wv, v)
    }
    {   const float4 v = TEXEL(1,1);
        const float wb = bx1*by1, wu = qu1*by1, wv = bx1*qv1;
        ACC4(T, wb, v) ACC4(Bu, wu, v) ACC4(Bv, wv, v)
    }
    {   const float4 v = TEXEL(2,1);
        ACC4(Bu, qu2*by1, v)
    }
    {   const float4 v = TEXEL(0,2);
        ACC4(Bv, bx0*qv2, v)
    }
    {   const float4 v = TEXEL(1,2);
        ACC4(Bv, bx1*qv2, v)
    }
    #undef TEXEL
    Bb.x += T.x; Bb.y += T.y; Bb.z += T.z; Bb.w += T.w;
    Bw.x += T.x; Bw.y += T.y; Bw.z += T.z; Bw.w += T.w;
}

// ---------------------------------------------------------------------------
// Kernel 2: 2 points per warp, 16 lanes/point, 4 channels/lane.
// Each 16-point block lies in exactly one ray (96 % 16 == 0).
// ---------------------------------------------------------------------------
__global__ __launch_bounds__(256, 5) void point_kernel(
        const float* __restrict__ b1,
        const float* __restrict__ b2,
        float* __restrict__ grad_out) {
    const int lane = threadIdx.x & 31;
    const int sub  = lane & 15;
    const int ray   = blockIdx.x / 6;                       // magic-mul, no div
    const int s     = (blockIdx.x - ray*6) * 16 + (threadIdx.x >> 5) * 2 + (lane >> 4);
    const int point = ray * SPR + s;

    const float4 A4 = g_rayp[ray*2];
    const float4 B4 = g_rayp[ray*2+1];
    const float frac = ((float)s + 0.5f) * (1.0f/96.0f);
    const float px = fmaf(B4.x, frac, A4.x);
    const float py = fmaf(B4.y, frac, A4.y);
    const float pz = fmaf(B4.z, frac, A4.z);
    const float pn2 = fmaf(px, px, fmaf(py, py, pz*pz));

    const Ax X = mkax(px);
    const Ax Y = mkax(py);
    const Ax Z = mkax(pz);

    // b1 baked into the accumulator init (each H receives +b1 exactly once)
    const float4 b1v = *reinterpret_cast<const float4*>(b1 + sub*4);
    float4 Hb = b1v, Hx = b1v, Hy = b1v, Hz = b1v;

    const float* PLL = g_PL + sub*4;
    // plane0 (x,y): base->Hb,Hz ; xFD->Hx ; yFD->Hy
    do_plane(PLL + ((size_t)0*PLANE_TEXELS + (size_t)Y.i1*PADW + X.i1)*HID,
             X, Y, Hb, Hz, Hx, Hy);
    // plane1 (x,z): base->Hb,Hy ; xFD->Hx ; zFD->Hz
    do_plane(PLL + ((size_t)1*PLANE_TEXELS + (size_t)Z.i1*PADW + X.i1)*HID,
             X, Z, Hb, Hy, Hx, Hz);
    // plane2 (y,z): base->Hb,Hx ; yFD->Hy ; zFD->Hz
    do_plane(PLL + ((size_t)2*PLANE_TEXELS + (size_t)Z.i1*PADW + Y.i1)*HID,
             Y, Z, Hb, Hx, Hy, Hz);

    // epilogue weights: transposed W2 columns (contiguous)
    const float4 wc0 = *reinterpret_cast<const float4*>(&g_W2T[0*64 + sub*4]);
    const float4 wc1 = *reinterpret_cast<const float4*>(&g_W2T[1*64 + sub*4]);
    const float4 wc2 = *reinterpret_cast<const float4*>(&g_W2T[2*64 + sub*4]);
    const float4 wc3 = *reinterpret_cast<const float4*>(&g_W2T[3*64 + sub*4]);

    const float hb0 = fmaxf(Hb.x, 0.f);
    const float hb1 = fmaxf(Hb.y, 0.f);
    const float hb2 = fmaxf(Hb.z, 0.f);
    const float hb3 = fmaxf(Hb.w, 0.f);
    const float hx0 = fmaxf(Hx.x, 0.f);
    const float hx1 = fmaxf(Hx.y, 0.f);
    const float hx2 = fmaxf(Hx.z, 0.f);
    const float hx3 = fmaxf(Hx.w, 0.f);
    const float hy0 = fmaxf(Hy.x, 0.f);
    const float hy1 = fmaxf(Hy.y, 0.f);
    const float hy2 = fmaxf(Hy.z, 0.f);
    const float hy3 = fmaxf(Hy.w, 0.f);
    const float hz0 = fmaxf(Hz.x, 0.f);
    const float hz1 = fmaxf(Hz.y, 0.f);
    const float hz2 = fmaxf(Hz.z, 0.f);
    const float hz3 = fmaxf(Hz.w, 0.f);

    const float v0 = fmaf(hb0,wc0.x, fmaf(hb1,wc0.y, fmaf(hb2,wc0.z, hb3*wc0.w)));
    const float v1 = fmaf(hb0,wc1.x, fmaf(hb1,wc1.y, fmaf(hb2,wc1.z, hb3*wc1.w)));
    const float v2 = fmaf(hb0,wc2.x, fmaf(hb1,wc2.y, fmaf(hb2,wc2.z, hb3*wc2.w)));
    const float v3 = fmaf(hb0,wc3.x, fmaf(hb1,wc3.y, fmaf(hb2,wc3.z, hb3*wc3.w)));
    const float vx = fmaf(hx0,wc0.x, fmaf(hx1,wc0.y, fmaf(hx2,wc0.z, hx3*wc0.w)));
    const float vy = fmaf(hy0,wc0.x, fmaf(hy1,wc0.y, fmaf(hy2,wc0.z, hy3*wc0.w)));
    const float vz = fmaf(hz0,wc0.x, fmaf(hz1,wc0.y, fmaf(hz2,wc0.z, hz3*wc0.w)));

    // --- packed multi-value reduction over 16 lanes (values: v0..v3,vx,vy,vz,0)
    const bool lo1 = (lane & 1) == 0;
    float s0 = lo1 ? vx : v0;
    float s1 = lo1 ? vy : v1;
    float s2 = lo1 ? vz : v2;
    float s3 = lo1 ? 0.f : v3;
    s0 = __shfl_xor_sync(0xffffffffu, s0, 1);
    s1 = __shfl_xor_sync(0xffffffffu, s1, 1);
    s2 = __shfl_xor_sync(0xffffffffu, s2, 1);
    s3 = __shfl_xor_sync(0xffffffffu, s3, 1);
    const float a0 = (lo1 ? v0 : vx) + s0;
    const float a1 = (lo1 ? v1 : vy) + s1;
    const float a2 = (lo1 ? v2 : vz) + s2;
    const float a3 = (lo1 ? v3 : 0.f) + s3;
    const bool lo2 = ((lane >> 1) & 1) == 0;
    float u0 = lo2 ? a2 : a0;
    float u1 = lo2 ? a3 : a1;
    u0 = __shfl_xor_sync(0xffffffffu, u0, 2);
    u1 = __shfl_xor_sync(0xffffffffu, u1, 2);
    const float c0 = (lo2 ? a0 : a2) + u0;
    const float c1 = (lo2 ? a1 : a3) + u1;
    const bool lo3 = ((lane >> 2) & 1) == 0;
    float w = lo3 ? c1 : c0;
    w = __shfl_xor_sync(0xffffffffu, w, 4);
    float dsum = (lo3 ? c0 : c1) + w;
    dsum += __shfl_xor_sync(0xffffffffu, dsum, 8);
    // value j lives at half-lane L(j) = bitrev3(j): {0,4,2,6,1,5,3,7}
    const int hb16 = lane & 16;
    const float4 b2v = *reinterpret_cast<const float4*>(b2);
    const float sdf_base = __shfl_sync(0xffffffffu, dsum, hb16 + 0) + b2v.x;
    const float rgb1v    = __shfl_sync(0xffffffffu, dsum, hb16 + 4) + b2v.y;
    const float rgb2v    = __shfl_sync(0xffffffffu, dsum, hb16 + 2) + b2v.z;
    const float rgb3v    = __shfl_sync(0xffffffffu, dsum, hb16 + 6) + b2v.w;
    const float sdfx     = __shfl_sync(0xffffffffu, dsum, hb16 + 1) + b2v.x;
    const float sdfy     = __shfl_sync(0xffffffffu, dsum, hb16 + 5) + b2v.x;
    const float sdfz     = __shfl_sync(0xffffffffu, dsum, hb16 + 3) + b2v.x;

    if (sub == 0) {
        const float g0 = (sdfx - sdf_base) * 100.f;
        const float g1 = (sdfy - sdf_base) * 100.f;
        const float g2 = (sdfz - sdf_base) * 100.f;
        grad_out[point*3 + 0] = g0;
        grad_out[point*3 + 1] = g1;
        grad_out[point*3 + 2] = g2;
        const float gn  = sqrtf(g0*g0 + g1*g1 + g2*g2);
        const float inv = __fdividef(1.f, gn + 1e-8f);
        const float shifted = sdf_base + sqrtf(pn2) - 0.5f;
        const float xs = -shifted * 80.f;
        const float sigma = fmaxf(xs, 0.f) + __logf(1.f + __expf(-fabsf(xs)));
        const float r1 = __fdividef(1.002f, 1.f + __expf(-rgb1v)) - 0.001f;
        const float r2 = __fdividef(1.002f, 1.f + __expf(-rgb2v)) - 0.001f;
        const float r3 = __fdividef(1.002f, 1.f + __expf(-rgb3v)) - 0.001f;
        float4 A; A.x = r1; A.y = r2; A.z = r3; A.w = sigma;
        float4 B; B.x = g0*inv; B.y = g1*inv; B.z = g2*inv; B.w = 0.f;
        *reinterpret_cast<float4*>(&g_scr[point*8    ]) = A;
        *reinterpret_cast<float4*>(&g_scr[point*8 + 4]) = B;
    }
}

// ---------------------------------------------------------------------------
// Kernel 3: warp-per-ray compositing via multiplicative prefix scan.
// ---------------------------------------------------------------------------
__global__ void composite(float* __restrict__ out) {
    const int lane = threadIdx.x & 31;
    const int r = blockIdx.x * 8 + (threadIdx.x >> 5);

    const float tn   = g_rayp[r*2].w;
    const float span = g_rayp[r*2+1].w;
    const float delta = span * (1.0f/96.0f);

    float rgb0=0.f, rgb1=0.f, rgb2=0.f, dep=0.f, ws=0.f, n0=0.f, n1=0.f, n2=0.f;
    float Tpre = 1.f;
    #pragma unroll
    for (int k = 0; k < 3; k++) {
        const int s = k*32 + lane;
        const float4 A = *reinterpret_cast<const float4*>(&g_scr[(size_t)(r*SPR + s)*8]);
        const float4 B = *reinterpret_cast<const float4*>(&g_scr[(size_t)(r*SPR + s)*8 + 4]);
        const float e = __expf(-A.w * delta);
        const float m = e + 1e-10f;
        const float alpha = 1.f - e;
        float incl = m;
        #pragma unroll
        for (int off = 1; off < 32; off <<= 1) {
            float t = __shfl_up_sync(0xffffffffu, incl, off);
            if (lane >= off) incl *= t;
        }
        float excl = __shfl_up_sync(0xffffffffu, incl, 1);
        if (lane == 0) excl = 1.f;
        const float tot = __shfl_sync(0xffffffffu, incl, 31);
        const float T = Tpre * excl;
        const float w = alpha * T;
        rgb0 = fmaf(w, A.x, rgb0);
        rgb1 = fmaf(w, A.y, rgb1);
        rgb2 = fmaf(w, A.z, rgb2);
        dep  = fmaf(w, tn + span * (((float)s + 0.5f) * (1.0f/96.0f)), dep);
        ws  += w;
        n0 = fmaf(w, B.x, n0);
        n1 = fmaf(w, B.y, n1);
        n2 = fmaf(w, B.z, n2);
        Tpre *= tot;
    }
    rgb0 = sum32(rgb0);
    rgb1 = sum32(rgb1);
    rgb2 = sum32(rgb2);
    dep  = sum32(dep);
    ws   = sum32(ws);
    n0   = sum32(n0);
    n1   = sum32(n1);
    n2   = sum32(n2);

    if (lane == 0) {
        const float bg = 1.f - ws;
        const float nn  = sqrtf(n0*n0 + n1*n1 + n2*n2);
        const float inv = __fdividef(1.f, nn + 1e-8f);
        out[r]         = rgb0 + bg;
        out[ 4096 + r] = rgb1 + bg;
        out[ 8192 + r] = rgb2 + bg;
        out[12288 + r] = dep;
        out[16384 + r] = ws;
        out[20480 + r] = ((n0*inv) + 1.f) * 0.5f * ws;
        out[24576 + r] = ((n1*inv) + 1.f) * 0.5f * ws;
        out[28672 + r] = ((n2*inv) + 1.f) * 0.5f * ws;
    }
}

// ---------------------------------------------------------------------------
extern "C" void kernel_launch(void* const* d_in, const int* in_sizes, int n_in,
                              void* d_out, int out_size) {
    const float* planes = (const float*)d_in[0];
    const float* ro     = (const float*)d_in[1];
    const float* rd     = (const float*)d_in[2];
    const float* W1     = (const float*)d_in[3];
    const float* b1     = (const float*)d_in[4];
    const float* W2     = (const float*)d_in[5];
    const float* b2     = (const float*)d_in[6];
    float* out = (float*)d_out;

    project_planes<<<GEMM_BLOCKS + SETUP_BLOCKS, 512>>>(planes, W1, W2, ro, rd);
    point_kernel<<<NPTS/16, 256>>>(b1, b2, out + 32768);
    composite<<<NRAY/8, 256>>>(out);
}